// round 16
// baseline (speedup 1.0000x reference)
#include <cuda_runtime.h>
#include <cstdint>

// z = sum_{p,q,r} C[p*9+q*3+r] * u0_p * u1_q * u2_r,  u_i = (1, cos x_i, sin x_i)
__device__ float d_C[27];

// ---------------------------------------------------------------------------
// Kernel 1: build the 27 trilinear coefficients from q_weights (18 floats).
// Single warp. All 18 sincos in parallel up front; A built 2 entries/lane;
// lanes 0..26 compute their coefficient directly from the 8 A-entries the
// sparse g-product touches (no reduction tree).
// ---------------------------------------------------------------------------
__global__ void build_coeffs(const float* __restrict__ qw) {
    __shared__ float Ure[8][8];   // [m][j]
    __shared__ float Uim[8][8];
    __shared__ float Aj[8][8];    // A[j][k]

    const unsigned FULL = 0xFFFFFFFFu;
    const int lane = threadIdx.x;

    float ang = (lane < 18) ? 0.5f * qw[lane] : 0.f;
    float sh, ch;
    __sincosf(ang, &sh, &ch);

    const int j = lane & 7;
    float sr[8], si[8];
    #pragma unroll
    for (int m = 0; m < 8; m++) { sr[m] = 0.f; si[m] = 0.f; }
    sr[j] = 1.0f;

    #pragma unroll
    for (int g = 0; g < 9; g++) {          // layer = g/3, qubit = g%3
        const int bit = 4 >> (g % 3);
        float cy = __shfl_sync(FULL, ch, 2 * g);
        float sy = __shfl_sync(FULL, sh, 2 * g);
        float cz = __shfl_sync(FULL, ch, 2 * g + 1);
        float sz = __shfl_sync(FULL, sh, 2 * g + 1);

        #pragma unroll
        for (int m = 0; m < 8; m++) {      // RY
            if (m & bit) continue;
            int m1 = m | bit;
            float ar = sr[m],  ai = si[m];
            float br = sr[m1], bi = si[m1];
            sr[m]  = cy * ar - sy * br;  si[m]  = cy * ai - sy * bi;
            sr[m1] = sy * ar + cy * br;  si[m1] = sy * ai + cy * bi;
        }
        #pragma unroll
        for (int m = 0; m < 8; m++) {      // RZ
            float ar = sr[m], ai = si[m];
            if (m & bit) { sr[m] = cz * ar - sz * ai; si[m] = cz * ai + sz * ar; }
            else         { sr[m] = cz * ar + sz * ai; si[m] = cz * ai - sz * ar; }
        }
        if (g % 3 == 2) {
            #pragma unroll
            for (int m = 4; m < 6; m++) {  // CNOT01: swap (4,6),(5,7)
                int m1 = m | 2; float tmp;
                tmp = sr[m]; sr[m] = sr[m1]; sr[m1] = tmp;
                tmp = si[m]; si[m] = si[m1]; si[m1] = tmp;
            }
            #pragma unroll
            for (int m = 2; m < 8; m += 4) { // CNOT12: swap (2,3),(6,7)
                int m1 = m | 1; float tmp;
                tmp = sr[m]; sr[m] = sr[m1]; sr[m1] = tmp;
                tmp = si[m]; si[m] = si[m1]; si[m1] = tmp;
            }
        }
    }

    if (lane < 8) {
        #pragma unroll
        for (int m = 0; m < 8; m++) { Ure[m][j] = sr[m]; Uim[m][j] = si[m]; }
    }
    __syncwarp();

    #pragma unroll
    for (int h = 0; h < 2; h++) {
        int e = lane + h * 32;
        int jj = e >> 3, kk = e & 7;
        float a = 0.f;
        #pragma unroll
        for (int m = 0; m < 8; m++) {
            float sgn = (m & 4) ? -1.f : 1.f;
            a += sgn * (Ure[m][jj] * Ure[m][kk] + Uim[m][jj] * Uim[m][kk]);
        }
        Aj[jj][kk] = a;
    }
    __syncwarp();

    // Sparse direct contraction: C[p,q,r] touches exactly 8 A-entries.
    if (lane < 27) {
        const int p = lane / 9, q = (lane / 3) % 3, r = lane % 3;
        float csum = 0.f;
        #pragma unroll
        for (int i0 = 0; i0 < 2; i0++) {
            int b0 = (p == 2) ? 1 - i0 : i0;
            float w0 = (p == 1 && i0 == 1) ? -0.5f : 0.5f;
            #pragma unroll
            for (int i1 = 0; i1 < 2; i1++) {
                int b1 = (q == 2) ? 1 - i1 : i1;
                float w1 = (q == 1 && i1 == 1) ? -0.5f : 0.5f;
                float w01 = w0 * w1;
                #pragma unroll
                for (int i2 = 0; i2 < 2; i2++) {
                    int b2 = (r == 2) ? 1 - i2 : i2;
                    float w2 = (r == 1 && i2 == 1) ? -0.5f : 0.5f;
                    csum = fmaf(w01 * w2,
                                Aj[i0 * 4 + i1 * 2 + i2][b0 * 4 + b1 * 2 + b2],
                                csum);
                }
            }
        }
        d_C[lane] = csum;
    }
}

// ---------------------------------------------------------------------------
// Kernel 2 (PDL): streaming loads -> ALL sincos -> grid-dependency sync ->
// trilinear -> streaming stores. Input/output are touch-once: __ldcs/__stcs
// (evict-first) keep L2 from wasting allocate cycles on dead lines.
// ---------------------------------------------------------------------------
static constexpr int SPT = 8;
static constexpr int BLOCK = 256;

__global__ void __launch_bounds__(BLOCK) vqc_eval(const float4* __restrict__ in,
                                                  float* __restrict__ out, int B) {
    const int T = gridDim.x * BLOCK;
    const int t = blockIdx.x * BLOCK + threadIdx.x;

    // Front-batch ALL loads (streaming).
    float4 x[SPT];
    #pragma unroll
    for (int k = 0; k < SPT; k++) {
        int i = t + k * T;
        i = (i < B) ? i : (B - 1);
        x[k] = __ldcs(&in[(size_t)i * 2]);   // first 16B of the 32B row
    }

    // All trig BEFORE the dependency sync — overlaps build_coeffs.
    float C0[SPT], S0[SPT], C1[SPT], S1[SPT], C2[SPT], S2[SPT];
    #pragma unroll
    for (int k = 0; k < SPT; k++) {
        __sincosf(x[k].x, &S0[k], &C0[k]);
        __sincosf(x[k].y, &S1[k], &C1[k]);
        __sincosf(x[k].z, &S2[k], &C2[k]);
    }

    cudaGridDependencySynchronize();

    __shared__ float cs[27];
    if (threadIdx.x < 27) cs[threadIdx.x] = d_C[threadIdx.x];
    __syncthreads();

    #pragma unroll
    for (int k = 0; k < SPT; k++) {
        float u0[3] = {1.f, C0[k], S0[k]};
        float u1[3] = {1.f, C1[k], S1[k]};
        float z = 0.f;
        #pragma unroll
        for (int p = 0; p < 3; p++) {
            #pragma unroll
            for (int q = 0; q < 3; q++) {
                const float* c3 = &cs[p * 9 + q * 3];
                float w = c3[0];
                w = fmaf(c3[1], C2[k], w);
                w = fmaf(c3[2], S2[k], w);
                z = fmaf(u0[p] * u1[q], w, z);
            }
        }
        int i = t + k * T;
        if (i < B) __stcs(&out[i], z);       // streaming store
    }
}

extern "C" void kernel_launch(void* const* d_in, const int* in_sizes, int n_in,
                              void* d_out, int out_size) {
    const float* inputs = (const float*)d_in[0];   // (B, 8) float32
    const float* qw     = (const float*)d_in[1];   // (3, 3, 2) float32
    float* out          = (float*)d_out;           // (B, 1) float32

    int B = in_sizes[0] / 8;

    build_coeffs<<<1, 32>>>(qw);

    int grid = (B + BLOCK * SPT - 1) / (BLOCK * SPT);   // 512 for B = 2^20

    cudaLaunchConfig_t cfg = {};
    cfg.gridDim = dim3(grid);
    cfg.blockDim = dim3(BLOCK);
    cfg.dynamicSmemBytes = 0;
    cudaLaunchAttribute attr[1];
    attr[0].id = cudaLaunchAttributeProgrammaticStreamSerialization;
    attr[0].val.programmaticStreamSerializationAllowed = 1;
    cfg.attrs = attr;
    cfg.numAttrs = 1;

    cudaLaunchKernelEx(&cfg, vqc_eval, (const float4*)inputs, out, B);
}

// round 17
// speedup vs baseline: 1.0030x; 1.0030x over previous
#include <cuda_runtime.h>
#include <cstdint>

// QuantumLayerVQC — final kernel.
//
// Math: the 3-qubit circuit factorizes into (per-sample RY encoding) x
// (sample-independent unitary from q_weights). <Z0> collapses to a trilinear
// form z = sum_{p,q,r} C[p*9+q*3+r] * u0_p * u1_q * u2_r with
// u_i = (1, cos x_i, sin x_i) and 27 coefficients built once from the 18
// weights. The eval kernel is then a pure 36 MB stream at the platform's
// measured ~3.4 TB/s ceiling for this 32 B/row shape (verified equal across
// LDG / cp.async.bulk / TMA-ring paths) — i.e. at the machine floor.
//
// Structure: build_coeffs (1 warp) + vqc_eval launched with Programmatic
// Dependent Launch; eval front-batches all loads and computes all trig
// BEFORE cudaGridDependencySynchronize(), fully hiding the build.

__device__ float d_C[27];

// ---------------------------------------------------------------------------
// Kernel 1: build the 27 trilinear coefficients from q_weights (18 floats).
// Single warp. All 18 sincos in parallel up front; A built 2 entries/lane;
// lanes 0..26 compute their coefficient directly from the 8 A-entries the
// sparse g-product touches (no reduction tree).
// ---------------------------------------------------------------------------
__global__ void build_coeffs(const float* __restrict__ qw) {
    __shared__ float Ure[8][8];   // [m][j]
    __shared__ float Uim[8][8];
    __shared__ float Aj[8][8];    // A[j][k]

    const unsigned FULL = 0xFFFFFFFFu;
    const int lane = threadIdx.x;

    float ang = (lane < 18) ? 0.5f * qw[lane] : 0.f;
    float sh, ch;
    __sincosf(ang, &sh, &ch);

    const int j = lane & 7;
    float sr[8], si[8];
    #pragma unroll
    for (int m = 0; m < 8; m++) { sr[m] = 0.f; si[m] = 0.f; }
    sr[j] = 1.0f;

    #pragma unroll
    for (int g = 0; g < 9; g++) {          // layer = g/3, qubit = g%3
        const int bit = 4 >> (g % 3);
        float cy = __shfl_sync(FULL, ch, 2 * g);
        float sy = __shfl_sync(FULL, sh, 2 * g);
        float cz = __shfl_sync(FULL, ch, 2 * g + 1);
        float sz = __shfl_sync(FULL, sh, 2 * g + 1);

        #pragma unroll
        for (int m = 0; m < 8; m++) {      // RY
            if (m & bit) continue;
            int m1 = m | bit;
            float ar = sr[m],  ai = si[m];
            float br = sr[m1], bi = si[m1];
            sr[m]  = cy * ar - sy * br;  si[m]  = cy * ai - sy * bi;
            sr[m1] = sy * ar + cy * br;  si[m1] = sy * ai + cy * bi;
        }
        #pragma unroll
        for (int m = 0; m < 8; m++) {      // RZ
            float ar = sr[m], ai = si[m];
            if (m & bit) { sr[m] = cz * ar - sz * ai; si[m] = cz * ai + sz * ar; }
            else         { sr[m] = cz * ar + sz * ai; si[m] = cz * ai - sz * ar; }
        }
        if (g % 3 == 2) {
            #pragma unroll
            for (int m = 4; m < 6; m++) {  // CNOT01: swap (4,6),(5,7)
                int m1 = m | 2; float tmp;
                tmp = sr[m]; sr[m] = sr[m1]; sr[m1] = tmp;
                tmp = si[m]; si[m] = si[m1]; si[m1] = tmp;
            }
            #pragma unroll
            for (int m = 2; m < 8; m += 4) { // CNOT12: swap (2,3),(6,7)
                int m1 = m | 1; float tmp;
                tmp = sr[m]; sr[m] = sr[m1]; sr[m1] = tmp;
                tmp = si[m]; si[m] = si[m1]; si[m1] = tmp;
            }
        }
    }

    if (lane < 8) {
        #pragma unroll
        for (int m = 0; m < 8; m++) { Ure[m][j] = sr[m]; Uim[m][j] = si[m]; }
    }
    __syncwarp();

    #pragma unroll
    for (int h = 0; h < 2; h++) {
        int e = lane + h * 32;
        int jj = e >> 3, kk = e & 7;
        float a = 0.f;
        #pragma unroll
        for (int m = 0; m < 8; m++) {
            float sgn = (m & 4) ? -1.f : 1.f;
            a += sgn * (Ure[m][jj] * Ure[m][kk] + Uim[m][jj] * Uim[m][kk]);
        }
        Aj[jj][kk] = a;
    }
    __syncwarp();

    // Sparse direct contraction: C[p,q,r] touches exactly 8 A-entries.
    // Per axis with component c, the allowed (a, b, weight) pairs:
    //   c==0: (i,i,+.5)   c==1: (i,i, i? -.5 : +.5)   c==2: (i,1-i,+.5)
    if (lane < 27) {
        const int p = lane / 9, q = (lane / 3) % 3, r = lane % 3;
        float csum = 0.f;
        #pragma unroll
        for (int i0 = 0; i0 < 2; i0++) {
            int b0 = (p == 2) ? 1 - i0 : i0;
            float w0 = (p == 1 && i0 == 1) ? -0.5f : 0.5f;
            #pragma unroll
            for (int i1 = 0; i1 < 2; i1++) {
                int b1 = (q == 2) ? 1 - i1 : i1;
                float w1 = (q == 1 && i1 == 1) ? -0.5f : 0.5f;
                float w01 = w0 * w1;
                #pragma unroll
                for (int i2 = 0; i2 < 2; i2++) {
                    int b2 = (r == 2) ? 1 - i2 : i2;
                    float w2 = (r == 1 && i2 == 1) ? -0.5f : 0.5f;
                    csum = fmaf(w01 * w2,
                                Aj[i0 * 4 + i1 * 2 + i2][b0 * 4 + b1 * 2 + b2],
                                csum);
                }
            }
        }
        d_C[lane] = csum;
    }
}

// ---------------------------------------------------------------------------
// Kernel 2 (PDL): loads -> ALL sincos -> grid-dependency sync -> trilinear.
// Everything before the sync is independent of build_coeffs, so the whole
// trig phase + the DRAM latency of the loads overlaps the build's execution.
// ---------------------------------------------------------------------------
static constexpr int SPT = 8;
static constexpr int BLOCK = 256;

__global__ void __launch_bounds__(BLOCK) vqc_eval(const float4* __restrict__ in,
                                                  float* __restrict__ out, int B) {
    const int T = gridDim.x * BLOCK;
    const int t = blockIdx.x * BLOCK + threadIdx.x;

    // Front-batch ALL loads.
    float4 x[SPT];
    #pragma unroll
    for (int k = 0; k < SPT; k++) {
        int i = t + k * T;
        i = (i < B) ? i : (B - 1);
        x[k] = in[(size_t)i * 2];     // first 16B of the 32B row
    }

    // All trig BEFORE the dependency sync — overlaps build_coeffs.
    float C0[SPT], S0[SPT], C1[SPT], S1[SPT], C2[SPT], S2[SPT];
    #pragma unroll
    for (int k = 0; k < SPT; k++) {
        __sincosf(x[k].x, &S0[k], &C0[k]);
        __sincosf(x[k].y, &S1[k], &C1[k]);
        __sincosf(x[k].z, &S2[k], &C2[k]);
    }

    cudaGridDependencySynchronize();

    __shared__ float cs[27];
    if (threadIdx.x < 27) cs[threadIdx.x] = d_C[threadIdx.x];
    __syncthreads();

    #pragma unroll
    for (int k = 0; k < SPT; k++) {
        float u0[3] = {1.f, C0[k], S0[k]};
        float u1[3] = {1.f, C1[k], S1[k]};
        float z = 0.f;
        #pragma unroll
        for (int p = 0; p < 3; p++) {
            #pragma unroll
            for (int q = 0; q < 3; q++) {
                const float* c3 = &cs[p * 9 + q * 3];
                float w = c3[0];
                w = fmaf(c3[1], C2[k], w);
                w = fmaf(c3[2], S2[k], w);
                z = fmaf(u0[p] * u1[q], w, z);
            }
        }
        int i = t + k * T;
        if (i < B) out[i] = z;
    }
}

extern "C" void kernel_launch(void* const* d_in, const int* in_sizes, int n_in,
                              void* d_out, int out_size) {
    const float* inputs = (const float*)d_in[0];   // (B, 8) float32
    const float* qw     = (const float*)d_in[1];   // (3, 3, 2) float32
    float* out          = (float*)d_out;           // (B, 1) float32

    int B = in_sizes[0] / 8;

    build_coeffs<<<1, 32>>>(qw);

    int grid = (B + BLOCK * SPT - 1) / (BLOCK * SPT);   // 512 for B = 2^20

    cudaLaunchConfig_t cfg = {};
    cfg.gridDim = dim3(grid);
    cfg.blockDim = dim3(BLOCK);
    cfg.dynamicSmemBytes = 0;
    cudaLaunchAttribute attr[1];
    attr[0].id = cudaLaunchAttributeProgrammaticStreamSerialization;
    attr[0].val.programmaticStreamSerializationAllowed = 1;
    cfg.attrs = attr;
    cfg.numAttrs = 1;

    cudaLaunchKernelEx(&cfg, vqc_eval, (const float4*)inputs, out, B);
}